// round 14
// baseline (speedup 1.0000x reference)
#include <cuda_runtime.h>
#include <cstdint>

#define BATCH 2
#define HEADS 16
#define SEQ   2048
#define DH    64
#define BQ    128
#define BK    32
#define NT    256

// tf32 RZ-truncation bias corrections (E[rel loss] = 2^-11 * E[1/m] ~ 3.52e-4)
#define CK_CORR 3.52e-4f            // K truncation, folded into Q scale
#define COUT_CORR 7.04e-4f          // P + V truncation, folded into Out scale

// smem row strides (floats)
#define WQ 68    // permuted pairs -> LDS.64 A-frags
#define WK 68    // natural -> K B-frags conflict-free (bank = 4g+t)
#define WV 68    // natural -> V A-frag LDS.32 conflict-free (bank = 8t+g)

#define SK_OFF   (128 * WQ)                    // 8704
#define SV_OFF   (SK_OFF + 2 * BK * WK)        // 13056
#define SINV_OFF (SV_OFF + 2 * BK * WV)        // 17408
#define SMEM_FLOATS (SINV_OFF + 128)           // 17536 floats = 70144 B -> 3 CTAs/SM

// permuted column within each 8-wide d-group: (t, t+4) -> (2t, 2t+1)
static __device__ __forceinline__ int pcol(int d) {
    return (d & 56) | ((d & 3) << 1) | ((d >> 2) & 1);
}

static __device__ __forceinline__ float to_tf32(float x) {
    uint32_t u;
    asm("cvt.rna.tf32.f32 %0, %1;" : "=r"(u) : "f"(x));
    return __uint_as_float(u);
}

static __device__ __forceinline__ uint32_t smem_u32(const void* p) {
    uint32_t a;
    asm("{ .reg .u64 t; cvta.to.shared.u64 t, %1; cvt.u32.u64 %0, t; }" : "=r"(a) : "l"(p));
    return a;
}

static __device__ __forceinline__ void cp16(uint32_t dst, const float* src) {
    asm volatile("cp.async.cg.shared.global [%0], [%1], 16;" :: "r"(dst), "l"(src));
}
#define CP_COMMIT() asm volatile("cp.async.commit_group;" ::: "memory")
#define CP_WAIT0()  asm volatile("cp.async.wait_group 0;" ::: "memory")

static __device__ __forceinline__ void mma8(float c[4], float a0, float a1,
                                            float a2, float a3, float b0, float b1) {
    uint32_t A0 = __float_as_uint(a0), A1 = __float_as_uint(a1);
    uint32_t A2 = __float_as_uint(a2), A3 = __float_as_uint(a3);
    uint32_t B0 = __float_as_uint(b0), B1 = __float_as_uint(b1);
    asm volatile(
        "mma.sync.aligned.m16n8k8.row.col.f32.tf32.tf32.f32 "
        "{%0,%1,%2,%3}, {%4,%5,%6,%7}, {%8,%9}, {%0,%1,%2,%3};\n"
        : "+f"(c[0]), "+f"(c[1]), "+f"(c[2]), "+f"(c[3])
        : "r"(A0), "r"(A1), "r"(A2), "r"(A3), "r"(B0), "r"(B1));
}

__global__ __launch_bounds__(NT, 3)
void attn_zovl_kernel(const float* __restrict__ Q, const float* __restrict__ K,
                      const float* __restrict__ V, float* __restrict__ Out,
                      float* __restrict__ Att)
{
    extern __shared__ float sm[];
    float* sQ   = sm;
    float* sK   = sm + SK_OFF;      // 2 stages of [BK][WK]
    float* sV   = sm + SV_OFF;      // 2 stages of [BK][WV]
    float* sInv = sm + SINV_OFF;

    const uint32_t sb = smem_u32(sm);

    const int tid  = threadIdx.x;
    const int w    = tid >> 5;
    const int lane = tid & 31;
    const int g    = lane >> 2;
    const int t    = lane & 3;
    const int qt   = (int)gridDim.x - 1 - (int)blockIdx.x;   // big tiles first
    const int bh   = blockIdx.y;
    const int q0   = qt * BQ;

    const int row_lo = (w << 4) + g;
    const int row_hi = row_lo + 8;
    const int qg_lo  = q0 + row_lo;
    const int qg_hi  = q0 + row_hi;

    const float* Qb = Q + (size_t)bh * SEQ * DH;
    const float* Kb = K + (size_t)bh * SEQ * DH;
    const float* Vb = V + (size_t)bh * SEQ * DH;
    float* attL = Att ? Att + ((size_t)bh * SEQ + qg_lo) * SEQ : nullptr;
    float* attH = Att ? Att + ((size_t)bh * SEQ + qg_hi) * SEQ : nullptr;

    // per-thread cp.async slice for one BK=32 tile: 2 chunks of 16B per matrix
    const int cpr = tid >> 4;            // 0..15 (rows cpr, cpr+16)
    const int cpc = (tid & 15) << 2;     // 0..60 step 4

    // ---- load Q tile once: scale (+ K-truncation correction), rna, permute
    const float qscale = 0.125f * (1.0f + CK_CORR);
    #pragma unroll
    for (int i = 0; i < 8; i++) {
        int idx = tid + i * NT;
        int r   = idx >> 4;
        int c4  = (idx & 15) << 2;
        float4 q4 = *(const float4*)(Qb + (size_t)(q0 + r) * DH + c4);
        sQ[r * WQ + pcol(c4 + 0)] = to_tf32(q4.x * qscale);
        sQ[r * WQ + pcol(c4 + 1)] = to_tf32(q4.y * qscale);
        sQ[r * WQ + pcol(c4 + 2)] = to_tf32(q4.z * qscale);
        sQ[r * WQ + pcol(c4 + 3)] = to_tf32(q4.w * qscale);
    }

    float l_lo = 0.0f, l_hi = 0.0f;
    // O^T accumulators: OT[mb][ng][4]; mb: d-block (16 d each), ng: q-octet
    float OT[4][2][4];
    #pragma unroll
    for (int mb = 0; mb < 4; mb++)
        #pragma unroll
        for (int ng = 0; ng < 2; ng++)
            #pragma unroll
            for (int j = 0; j < 4; j++) OT[mb][ng][j] = 0.0f;

    const int ntiles = 4 * qt + 4;       // 32-wide k tiles covering q0..q0+127

    // zero-region geometry (upper triangle: cols >= zstart, all 128 rows).
    // Interleaved into the mainloop: tile kt zeroes rows [kt*zrpt, (kt+1)*zrpt).
    const int zstart = (qt + 1) * BQ;
    const int zlen4  = (SEQ - zstart) >> 2;          // float4s per row (may be 0)
    const int zrpt   = (BQ + ntiles - 1) / ntiles;   // rows per tile iteration

    // ---- prologue: issue cp.async for tile 0 into stage 0 ------------------
    {
        const uint32_t kb = sb + SK_OFF * 4;
        const uint32_t vb = sb + SV_OFF * 4;
        #pragma unroll
        for (int j = 0; j < 2; j++) {
            int r = cpr + (j << 4);
            cp16(kb + (uint32_t)(r * WK + cpc) * 4, Kb + (size_t)r * DH + cpc);
            cp16(vb + (uint32_t)(r * WV + cpc) * 4, Vb + (size_t)r * DH + cpc);
        }
        CP_COMMIT();
    }

    for (int kt = 0; kt < ntiles; kt++) {
        const int b  = kt & 1;
        const int k0 = kt << 5;

        CP_WAIT0();                      // tile kt landed (own chunks)
        __syncthreads();                 // all chunks visible; other stage free

        // issue cp.async for tile kt+1 into the other stage (safe post-sync)
        if (kt + 1 < ntiles) {
            const int nk0 = k0 + BK;
            const uint32_t kb = sb + (uint32_t)(SK_OFF + (b ^ 1) * BK * WK) * 4;
            const uint32_t vb = sb + (uint32_t)(SV_OFF + (b ^ 1) * BK * WV) * 4;
            #pragma unroll
            for (int j = 0; j < 2; j++) {
                int r = cpr + (j << 4);
                cp16(kb + (uint32_t)(r * WK + cpc) * 4, Kb + (size_t)(nk0 + r) * DH + cpc);
                cp16(vb + (uint32_t)(r * WV + cpc) * 4, Vb + (size_t)(nk0 + r) * DH + cpc);
            }
        }
        CP_COMMIT();                     // (empty group on last iter is fine)

        // ---- overlapped zero-stores: this tile's slice of the masked region.
        // Pure stores, no dependency on l; they ride the idle DRAM bandwidth
        // of the compute phase. Anti-correlated sizing: small-qt CTAs have
        // short mainloops but big zero regions (and vice versa).
        if (Att && zlen4 > 0) {
            const int r0 = kt * zrpt;
            const int r1 = (r0 + zrpt < BQ) ? r0 + zrpt : BQ;
            const float4 z = make_float4(0.f, 0.f, 0.f, 0.f);
            for (int r = r0 + w; r < r1; r += 8) {
                float* rowp = Att + ((size_t)bh * SEQ + q0 + r) * SEQ + zstart;
                #pragma unroll 4
                for (int c = lane; c < zlen4; c += 32)
                    *(float4*)(rowp + (c << 2)) = z;
            }
        }

        const float* bK = sK + b * BK * WK;
        const float* bV = sV + b * BK * WV;

        // ---- QK^T: S[4][4] covers 16 q-rows x 32 k-cols --------------------
        float S[4][4];
        #pragma unroll
        for (int nf = 0; nf < 4; nf++)
            #pragma unroll
            for (int j = 0; j < 4; j++) S[nf][j] = 0.0f;

        #pragma unroll
        for (int ks = 0; ks < 8; ks++) {
            float2 aL = *(const float2*)&sQ[row_lo * WQ + (ks << 3) + (t << 1)];
            float2 aH = *(const float2*)&sQ[row_hi * WQ + (ks << 3) + (t << 1)];
            #pragma unroll
            for (int nf = 0; nf < 4; nf++) {
                float b0 = bK[((nf << 3) + g) * WK + (ks << 3) + t];
                float b1 = bK[((nf << 3) + g) * WK + (ks << 3) + t + 4];
                mma8(S[nf], aL.x, aH.x, aL.y, aH.y, b0, b1);
            }
        }

        // ---- P̃ = exp(S); masking only needed on diagonal-overlap tiles -----
        if (kt < (qt << 2)) {
            #pragma unroll
            for (int nf = 0; nf < 4; nf++) {
                float p0 = __expf(S[nf][0]);
                float p1 = __expf(S[nf][1]);
                float p2 = __expf(S[nf][2]);
                float p3 = __expf(S[nf][3]);
                l_lo += p0 + p1;
                l_hi += p2 + p3;
                int c0 = k0 + (nf << 3) + (t << 1);
                if (attL) {
                    *(float2*)&attL[c0] = make_float2(p0, p1);
                    *(float2*)&attH[c0] = make_float2(p2, p3);
                }
                S[nf][0] = p0; S[nf][1] = p1; S[nf][2] = p2; S[nf][3] = p3;
            }
        } else {
            #pragma unroll
            for (int nf = 0; nf < 4; nf++) {
                int c0 = k0 + (nf << 3) + (t << 1);
                int c1 = c0 + 1;
                float p0 = (c0 <= qg_lo) ? __expf(S[nf][0]) : 0.0f;
                float p1 = (c1 <= qg_lo) ? __expf(S[nf][1]) : 0.0f;
                float p2 = (c0 <= qg_hi) ? __expf(S[nf][2]) : 0.0f;
                float p3 = (c1 <= qg_hi) ? __expf(S[nf][3]) : 0.0f;
                l_lo += p0 + p1;
                l_hi += p2 + p3;
                if (attL) {
                    *(float2*)&attL[c0] = make_float2(p0, p1);
                    *(float2*)&attH[c0] = make_float2(p2, p3);
                }
                S[nf][0] = p0; S[nf][1] = p1; S[nf][2] = p2; S[nf][3] = p3;
            }
        }

        // ---- PV as O^T = V^T P^T: P C-frags feed B directly (no shuffles) --
        #pragma unroll
        for (int kc = 0; kc < 4; kc++) {
            const float* vr0 = &bV[((kc << 3) + (t << 1)) * WV];
            const float* vr1 = vr0 + WV;
            #pragma unroll
            for (int mb = 0; mb < 4; mb++) {
                int d0 = (mb << 4) + g;
                float a0 = vr0[d0];
                float a1 = vr0[d0 + 8];
                float a2 = vr1[d0];
                float a3 = vr1[d0 + 8];
                mma8(OT[mb][0], a0, a1, a2, a3, S[kc][0], S[kc][1]);
                mma8(OT[mb][1], a0, a1, a2, a3, S[kc][2], S[kc][3]);
            }
        }
    }

    // ---- reduce l across the quad; stage 1/l in smem ----------------------
    #pragma unroll
    for (int off = 1; off <= 2; off <<= 1) {
        l_lo += __shfl_xor_sync(0xffffffffu, l_lo, off);
        l_hi += __shfl_xor_sync(0xffffffffu, l_hi, off);
    }
    sInv[row_lo] = 1.0f / l_lo;
    sInv[row_hi] = 1.0f / l_hi;
    __syncthreads();                     // sInv visible; Att writes done

    // ---- O writeback (transposed regs; normalized + bias correction) ------
    if (Out) {
        const int qA = (w << 4) + (t << 1);       // ng0 q rows: qA, qA+1
        const int qB = qA + 8;                    // ng1 q rows: qB, qB+1
        const float iA0 = sInv[qA]     * (1.0f + COUT_CORR);
        const float iA1 = sInv[qA + 1] * (1.0f + COUT_CORR);
        const float iB0 = sInv[qB]     * (1.0f + COUT_CORR);
        const float iB1 = sInv[qB + 1] * (1.0f + COUT_CORR);
        float* outA0 = Out + ((size_t)bh * SEQ + q0 + qA) * DH;
        float* outA1 = outA0 + DH;
        float* outB0 = Out + ((size_t)bh * SEQ + q0 + qB) * DH;
        float* outB1 = outB0 + DH;
        #pragma unroll
        for (int mb = 0; mb < 4; mb++) {
            int d0 = (mb << 4) + g;
            outA0[d0]     = OT[mb][0][0] * iA0;
            outA1[d0]     = OT[mb][0][1] * iA1;
            outA0[d0 + 8] = OT[mb][0][2] * iA0;
            outA1[d0 + 8] = OT[mb][0][3] * iA1;
            outB0[d0]     = OT[mb][1][0] * iB0;
            outB1[d0]     = OT[mb][1][1] * iB1;
            outB0[d0 + 8] = OT[mb][1][2] * iB0;
            outB1[d0 + 8] = OT[mb][1][3] * iB1;
        }
    }

    // ---- epilogue: normalize lower-triangle rows only (zeros already done).
    // Warp-per-row, lane-strided, unroll 8 -> 8 independent LDG.128 in flight.
    if (Att) {
        const int n4 = zstart >> 2;              // float4s to normalize per row
        for (int r = w; r < BQ; r += 8) {
            const float s = sInv[r];
            float* rowp = Att + ((size_t)bh * SEQ + q0 + r) * SEQ;
            #pragma unroll 8
            for (int c = lane; c < n4; c += 32) {
                float4 v = *(float4*)(rowp + (c << 2));
                v.x *= s; v.y *= s; v.z *= s; v.w *= s;
                *(float4*)(rowp + (c << 2)) = v;
            }
        }
    }
}

extern "C" void kernel_launch(void* const* d_in, const int* in_sizes, int n_in,
                              void* d_out, int out_size) {
    const float* Q = (const float*)d_in[0];
    const float* K = (const float*)d_in[1];
    const float* V = (const float*)d_in[2];

    const long long OUT_E = (long long)BATCH * HEADS * SEQ * DH;
    const long long ATT_E = (long long)BATCH * HEADS * SEQ * SEQ;

    float* out_ptr = nullptr;
    float* att_ptr = nullptr;
    if ((long long)out_size == OUT_E + ATT_E) {
        out_ptr = (float*)d_out;
        att_ptr = (float*)d_out + OUT_E;
    } else if ((long long)out_size == OUT_E) {
        out_ptr = (float*)d_out;
    } else {
        att_ptr = (float*)d_out;
    }

    const int smem_bytes = SMEM_FLOATS * sizeof(float);   // 70144
    cudaFuncSetAttribute(attn_zovl_kernel,
                         cudaFuncAttributeMaxDynamicSharedMemorySize, smem_bytes);

    dim3 grid(SEQ / BQ, BATCH * HEADS);
    attn_zovl_kernel<<<grid, NT, smem_bytes>>>(Q, K, V, out_ptr, att_ptr);
}

// round 15
// speedup vs baseline: 1.1207x; 1.1207x over previous
#include <cuda_runtime.h>
#include <cstdint>

#define BATCH 2
#define HEADS 16
#define SEQ   2048
#define DH    64
#define BQ    128
#define BK    32
#define NT    256

// tf32 RZ-truncation bias corrections (E[rel loss] = 2^-11 * E[1/m] ~ 3.52e-4)
#define CK_CORR 3.52e-4f            // K truncation, folded into Q scale
#define COUT_CORR 7.04e-4f          // P + V truncation, folded into Out scale

// smem row strides (floats)
#define WQ 68    // permuted pairs -> LDS.64 A-frags
#define WK 68    // natural -> K B-frags conflict-free (bank = 4g+t)
#define WV 68    // natural -> V A-frag LDS.32 conflict-free (bank = 8t+g)

#define SK_OFF   (128 * WQ)                    // 8704
#define SV_OFF   (SK_OFF + 2 * BK * WK)        // 13056
#define SINV_OFF (SV_OFF + 2 * BK * WV)        // 17408
#define SMEM_FLOATS (SINV_OFF + 128)           // 17536 floats = 70144 B -> 3 CTAs/SM

// permuted column within each 8-wide d-group: (t, t+4) -> (2t, 2t+1)
static __device__ __forceinline__ int pcol(int d) {
    return (d & 56) | ((d & 3) << 1) | ((d >> 2) & 1);
}

static __device__ __forceinline__ float to_tf32(float x) {
    uint32_t u;
    asm("cvt.rna.tf32.f32 %0, %1;" : "=r"(u) : "f"(x));
    return __uint_as_float(u);
}

static __device__ __forceinline__ uint32_t smem_u32(const void* p) {
    uint32_t a;
    asm("{ .reg .u64 t; cvta.to.shared.u64 t, %1; cvt.u32.u64 %0, t; }" : "=r"(a) : "l"(p));
    return a;
}

static __device__ __forceinline__ void cp16(uint32_t dst, const float* src) {
    asm volatile("cp.async.cg.shared.global [%0], [%1], 16;" :: "r"(dst), "l"(src));
}
#define CP_COMMIT() asm volatile("cp.async.commit_group;" ::: "memory")
#define CP_WAIT0()  asm volatile("cp.async.wait_group 0;" ::: "memory")

// streaming (evict-first) global accessors — keep zero-reuse flows out of L2
static __device__ __forceinline__ void stg128_cs(float* p, float4 v) {
    asm volatile("st.global.cs.v4.f32 [%0], {%1,%2,%3,%4};"
                 :: "l"(p), "f"(v.x), "f"(v.y), "f"(v.z), "f"(v.w) : "memory");
}
static __device__ __forceinline__ float4 ldg128_cs(const float* p) {
    float4 v;
    asm volatile("ld.global.cs.v4.f32 {%0,%1,%2,%3}, [%4];"
                 : "=f"(v.x), "=f"(v.y), "=f"(v.z), "=f"(v.w) : "l"(p));
    return v;
}

static __device__ __forceinline__ void mma8(float c[4], float a0, float a1,
                                            float a2, float a3, float b0, float b1) {
    uint32_t A0 = __float_as_uint(a0), A1 = __float_as_uint(a1);
    uint32_t A2 = __float_as_uint(a2), A3 = __float_as_uint(a3);
    uint32_t B0 = __float_as_uint(b0), B1 = __float_as_uint(b1);
    asm volatile(
        "mma.sync.aligned.m16n8k8.row.col.f32.tf32.tf32.f32 "
        "{%0,%1,%2,%3}, {%4,%5,%6,%7}, {%8,%9}, {%0,%1,%2,%3};\n"
        : "+f"(c[0]), "+f"(c[1]), "+f"(c[2]), "+f"(c[3])
        : "r"(A0), "r"(A1), "r"(A2), "r"(A3), "r"(B0), "r"(B1));
}

__global__ __launch_bounds__(NT, 3)
void attn_l2_kernel(const float* __restrict__ Q, const float* __restrict__ K,
                    const float* __restrict__ V, float* __restrict__ Out,
                    float* __restrict__ Att)
{
    extern __shared__ float sm[];
    float* sQ   = sm;
    float* sK   = sm + SK_OFF;      // 2 stages of [BK][WK]
    float* sV   = sm + SV_OFF;      // 2 stages of [BK][WV]
    float* sInv = sm + SINV_OFF;

    const uint32_t sb = smem_u32(sm);

    const int tid  = threadIdx.x;
    const int w    = tid >> 5;
    const int lane = tid & 31;
    const int g    = lane >> 2;
    const int t    = lane & 3;
    const int qt   = (int)gridDim.x - 1 - (int)blockIdx.x;   // big tiles first
    const int bh   = blockIdx.y;
    const int q0   = qt * BQ;

    const int row_lo = (w << 4) + g;
    const int row_hi = row_lo + 8;
    const int qg_lo  = q0 + row_lo;
    const int qg_hi  = q0 + row_hi;

    const float* Qb = Q + (size_t)bh * SEQ * DH;
    const float* Kb = K + (size_t)bh * SEQ * DH;
    const float* Vb = V + (size_t)bh * SEQ * DH;
    float* attL = Att ? Att + ((size_t)bh * SEQ + qg_lo) * SEQ : nullptr;
    float* attH = Att ? Att + ((size_t)bh * SEQ + qg_hi) * SEQ : nullptr;

    // per-thread cp.async slice for one BK=32 tile: 2 chunks of 16B per matrix
    const int cpr = tid >> 4;            // 0..15 (rows cpr, cpr+16)
    const int cpc = (tid & 15) << 2;     // 0..60 step 4

    // ---- load Q tile once: scale (+ K-truncation correction), rna, permute
    const float qscale = 0.125f * (1.0f + CK_CORR);
    #pragma unroll
    for (int i = 0; i < 8; i++) {
        int idx = tid + i * NT;
        int r   = idx >> 4;
        int c4  = (idx & 15) << 2;
        float4 q4 = *(const float4*)(Qb + (size_t)(q0 + r) * DH + c4);
        sQ[r * WQ + pcol(c4 + 0)] = to_tf32(q4.x * qscale);
        sQ[r * WQ + pcol(c4 + 1)] = to_tf32(q4.y * qscale);
        sQ[r * WQ + pcol(c4 + 2)] = to_tf32(q4.z * qscale);
        sQ[r * WQ + pcol(c4 + 3)] = to_tf32(q4.w * qscale);
    }

    float l_lo = 0.0f, l_hi = 0.0f;
    // O^T accumulators: OT[mb][ng][4]; mb: d-block (16 d each), ng: q-octet
    float OT[4][2][4];
    #pragma unroll
    for (int mb = 0; mb < 4; mb++)
        #pragma unroll
        for (int ng = 0; ng < 2; ng++)
            #pragma unroll
            for (int j = 0; j < 4; j++) OT[mb][ng][j] = 0.0f;

    const int ntiles = 4 * qt + 4;       // 32-wide k tiles covering q0..q0+127

    // ---- prologue: issue cp.async for tile 0 into stage 0 ------------------
    {
        const uint32_t kb = sb + SK_OFF * 4;
        const uint32_t vb = sb + SV_OFF * 4;
        #pragma unroll
        for (int j = 0; j < 2; j++) {
            int r = cpr + (j << 4);
            cp16(kb + (uint32_t)(r * WK + cpc) * 4, Kb + (size_t)r * DH + cpc);
            cp16(vb + (uint32_t)(r * WV + cpc) * 4, Vb + (size_t)r * DH + cpc);
        }
        CP_COMMIT();
    }

    for (int kt = 0; kt < ntiles; kt++) {
        const int b  = kt & 1;
        const int k0 = kt << 5;

        CP_WAIT0();                      // tile kt landed (own chunks)
        __syncthreads();                 // all chunks visible; other stage free

        // issue cp.async for tile kt+1 into the other stage (safe post-sync)
        if (kt + 1 < ntiles) {
            const int nk0 = k0 + BK;
            const uint32_t kb = sb + (uint32_t)(SK_OFF + (b ^ 1) * BK * WK) * 4;
            const uint32_t vb = sb + (uint32_t)(SV_OFF + (b ^ 1) * BK * WV) * 4;
            #pragma unroll
            for (int j = 0; j < 2; j++) {
                int r = cpr + (j << 4);
                cp16(kb + (uint32_t)(r * WK + cpc) * 4, Kb + (size_t)(nk0 + r) * DH + cpc);
                cp16(vb + (uint32_t)(r * WV + cpc) * 4, Vb + (size_t)(nk0 + r) * DH + cpc);
            }
        }
        CP_COMMIT();                     // (empty group on last iter is fine)

        const float* bK = sK + b * BK * WK;
        const float* bV = sV + b * BK * WV;

        // ---- QK^T: S[4][4] covers 16 q-rows x 32 k-cols --------------------
        float S[4][4];
        #pragma unroll
        for (int nf = 0; nf < 4; nf++)
            #pragma unroll
            for (int j = 0; j < 4; j++) S[nf][j] = 0.0f;

        #pragma unroll
        for (int ks = 0; ks < 8; ks++) {
            float2 aL = *(const float2*)&sQ[row_lo * WQ + (ks << 3) + (t << 1)];
            float2 aH = *(const float2*)&sQ[row_hi * WQ + (ks << 3) + (t << 1)];
            #pragma unroll
            for (int nf = 0; nf < 4; nf++) {
                float b0 = bK[((nf << 3) + g) * WK + (ks << 3) + t];
                float b1 = bK[((nf << 3) + g) * WK + (ks << 3) + t + 4];
                mma8(S[nf], aL.x, aH.x, aL.y, aH.y, b0, b1);
            }
        }

        // ---- P̃ = exp(S); masking only needed on diagonal-overlap tiles -----
        if (kt < (qt << 2)) {
            #pragma unroll
            for (int nf = 0; nf < 4; nf++) {
                float p0 = __expf(S[nf][0]);
                float p1 = __expf(S[nf][1]);
                float p2 = __expf(S[nf][2]);
                float p3 = __expf(S[nf][3]);
                l_lo += p0 + p1;
                l_hi += p2 + p3;
                int c0 = k0 + (nf << 3) + (t << 1);
                if (attL) {
                    *(float2*)&attL[c0] = make_float2(p0, p1);
                    *(float2*)&attH[c0] = make_float2(p2, p3);
                }
                S[nf][0] = p0; S[nf][1] = p1; S[nf][2] = p2; S[nf][3] = p3;
            }
        } else {
            #pragma unroll
            for (int nf = 0; nf < 4; nf++) {
                int c0 = k0 + (nf << 3) + (t << 1);
                int c1 = c0 + 1;
                float p0 = (c0 <= qg_lo) ? __expf(S[nf][0]) : 0.0f;
                float p1 = (c1 <= qg_lo) ? __expf(S[nf][1]) : 0.0f;
                float p2 = (c0 <= qg_hi) ? __expf(S[nf][2]) : 0.0f;
                float p3 = (c1 <= qg_hi) ? __expf(S[nf][3]) : 0.0f;
                l_lo += p0 + p1;
                l_hi += p2 + p3;
                if (attL) {
                    *(float2*)&attL[c0] = make_float2(p0, p1);
                    *(float2*)&attH[c0] = make_float2(p2, p3);
                }
                S[nf][0] = p0; S[nf][1] = p1; S[nf][2] = p2; S[nf][3] = p3;
            }
        }

        // ---- PV as O^T = V^T P^T: P C-frags feed B directly (no shuffles) --
        #pragma unroll
        for (int kc = 0; kc < 4; kc++) {
            const float* vr0 = &bV[((kc << 3) + (t << 1)) * WV];
            const float* vr1 = vr0 + WV;
            #pragma unroll
            for (int mb = 0; mb < 4; mb++) {
                int d0 = (mb << 4) + g;
                float a0 = vr0[d0];
                float a1 = vr0[d0 + 8];
                float a2 = vr1[d0];
                float a3 = vr1[d0 + 8];
                mma8(OT[mb][0], a0, a1, a2, a3, S[kc][0], S[kc][1]);
                mma8(OT[mb][1], a0, a1, a2, a3, S[kc][2], S[kc][3]);
            }
        }
    }

    // ---- reduce l across the quad; stage 1/l in smem ----------------------
    #pragma unroll
    for (int off = 1; off <= 2; off <<= 1) {
        l_lo += __shfl_xor_sync(0xffffffffu, l_lo, off);
        l_hi += __shfl_xor_sync(0xffffffffu, l_hi, off);
    }
    sInv[row_lo] = 1.0f / l_lo;
    sInv[row_hi] = 1.0f / l_hi;
    __syncthreads();                     // sInv visible; Att writes done

    // ---- O writeback (transposed regs; normalized + bias correction) ------
    if (Out) {
        const int qA = (w << 4) + (t << 1);       // ng0 q rows: qA, qA+1
        const int qB = qA + 8;                    // ng1 q rows: qB, qB+1
        const float iA0 = sInv[qA]     * (1.0f + COUT_CORR);
        const float iA1 = sInv[qA + 1] * (1.0f + COUT_CORR);
        const float iB0 = sInv[qB]     * (1.0f + COUT_CORR);
        const float iB1 = sInv[qB + 1] * (1.0f + COUT_CORR);
        float* outA0 = Out + ((size_t)bh * SEQ + q0 + qA) * DH;
        float* outA1 = outA0 + DH;
        float* outB0 = Out + ((size_t)bh * SEQ + q0 + qB) * DH;
        float* outB1 = outB0 + DH;
        #pragma unroll
        for (int mb = 0; mb < 4; mb++) {
            int d0 = (mb << 4) + g;
            outA0[d0]     = OT[mb][0][0] * iA0;
            outA1[d0]     = OT[mb][0][1] * iA1;
            outA0[d0 + 8] = OT[mb][0][2] * iA0;
            outA1[d0 + 8] = OT[mb][0][3] * iA1;
            outB0[d0]     = OT[mb][1][0] * iB0;
            outB1[d0]     = OT[mb][1][1] * iB1;
            outB0[d0 + 8] = OT[mb][1][2] * iB0;
            outB1[d0 + 8] = OT[mb][1][3] * iB1;
        }
    }

    // ---- epilogue: warp-per-row normalize + zero (round-12 structure) -----
    // Cache policy: re-read .cs (read-once, self-evicting), writes .cs
    // (never re-read) — keeps L2 available for other CTAs' pending P̃ re-reads.
    if (Att) {
        const int zstart = (qt + 1) * BQ;        // first masked column
        const int n4   = zstart >> 2;            // float4s to normalize
        const int s4   = SEQ >> 2;               // float4s per full row
        const float4 z = make_float4(0.f, 0.f, 0.f, 0.f);
        for (int r = w; r < BQ; r += 8) {
            const float s = sInv[r];
            float* rowp = Att + ((size_t)bh * SEQ + q0 + r) * SEQ;
            #pragma unroll 4
            for (int c = lane; c < n4; c += 32) {
                float4 v = ldg128_cs(rowp + (c << 2));
                v.x *= s; v.y *= s; v.z *= s; v.w *= s;
                stg128_cs(rowp + (c << 2), v);
            }
            #pragma unroll 4
            for (int c = n4 + lane; c < s4; c += 32)
                stg128_cs(rowp + (c << 2), z);
        }
    }
}

extern "C" void kernel_launch(void* const* d_in, const int* in_sizes, int n_in,
                              void* d_out, int out_size) {
    const float* Q = (const float*)d_in[0];
    const float* K = (const float*)d_in[1];
    const float* V = (const float*)d_in[2];

    const long long OUT_E = (long long)BATCH * HEADS * SEQ * DH;
    const long long ATT_E = (long long)BATCH * HEADS * SEQ * SEQ;

    float* out_ptr = nullptr;
    float* att_ptr = nullptr;
    if ((long long)out_size == OUT_E + ATT_E) {
        out_ptr = (float*)d_out;
        att_ptr = (float*)d_out + OUT_E;
    } else if ((long long)out_size == OUT_E) {
        out_ptr = (float*)d_out;
    } else {
        att_ptr = (float*)d_out;
    }

    const int smem_bytes = SMEM_FLOATS * sizeof(float);   // 70144
    cudaFuncSetAttribute(attn_l2_kernel,
                         cudaFuncAttributeMaxDynamicSharedMemorySize, smem_bytes);

    dim3 grid(SEQ / BQ, BATCH * HEADS);
    attn_l2_kernel<<<grid, NT, smem_bytes>>>(Q, K, V, out_ptr, att_ptr);
}